// round 16
// baseline (speedup 1.0000x reference)
#include <cuda_runtime.h>
#include <cuda_fp16.h>
#include <math.h>
#include <stdint.h>

// ---------------------------------------------------------------------------
// Problem constants
// ---------------------------------------------------------------------------
#define NB   32
#define NL   4096
#define NH   512
#define NC   1025
#define MTOT (NB * NL)   // 131072

#define MT2  256         // m rows per CTA
#define NST  16          // 4 h-tiles x 4 k-stages of 128

// SMEM layout (GEMM): A/B tiles with 272B rows (128 fp16 + 16B pad)
#define ROW2    272
#define A_TILE  (256 * ROW2)            // 69632
#define B_TILE  (128 * ROW2)            // 34816
#define SM_B    (2 * A_TILE)            // 139264
#define SM_TAB  (2 * A_TILE + 2 * B_TILE)  // 208896
// tables: w2[512] base[512] wcov[512] red[256*4]
#define SMEM_TOTAL (SM_TAB + 10240)     // 219136

// ---------------------------------------------------------------------------
// Device scratch (static; no runtime allocation)
// ---------------------------------------------------------------------------
__device__ float g_base[NB * NH];
__device__ float g_logits[MTOT];
__device__ __half g_Bf[NH * 512];             // W1[:,0:512] fp16
__device__ float g_ctx_part[32 * NB * 512];
__device__ int g_work[512];                   // GEMM worklist (b<<4)|tile256
__device__ int g_nwork;
__device__ int g_work2[1024];                 // ctx worklist (b<<5)|tile128
__device__ int g_nwork2;

// ---------------------------------------------------------------------------
// helpers
// ---------------------------------------------------------------------------
__device__ __forceinline__ uint32_t smem_u32(const void* p) {
    uint32_t a;
    asm("{ .reg .u64 t; cvta.to.shared.u64 t, %1; cvt.u32.u64 %0, t; }"
        : "=r"(a) : "l"(p));
    return a;
}

__device__ __forceinline__ void ldsm4(uint32_t addr, uint32_t& r0, uint32_t& r1,
                                      uint32_t& r2, uint32_t& r3) {
    asm volatile("ldmatrix.sync.aligned.m8n8.x4.shared.b16 {%0,%1,%2,%3}, [%4];"
                 : "=r"(r0), "=r"(r1), "=r"(r2), "=r"(r3) : "r"(addr));
}

__device__ __forceinline__ void mma16816(float* d, uint32_t a0, uint32_t a1,
                                         uint32_t a2, uint32_t a3, uint32_t b0,
                                         uint32_t b1) {
    asm volatile(
        "mma.sync.aligned.m16n8k16.row.col.f32.f16.f16.f32 "
        "{%0,%1,%2,%3}, {%4,%5,%6,%7}, {%8,%9}, {%0,%1,%2,%3};"
        : "+f"(d[0]), "+f"(d[1]), "+f"(d[2]), "+f"(d[3])
        : "r"(a0), "r"(a1), "r"(a2), "r"(a3), "r"(b0), "r"(b1));
}

__device__ __forceinline__ void cpasync16(uint32_t dst, const void* src) {
    asm volatile("cp.async.cg.shared.global [%0], [%1], 16;"
                 :: "r"(dst), "l"(src) : "memory");
}
#define CP_COMMIT() asm volatile("cp.async.commit_group;" ::: "memory")
#define CP_WAIT0()  asm volatile("cp.async.wait_group 0;" ::: "memory")

__device__ __forceinline__ float fast_tanh(float x) {
    float t = x * 2.885390081777927f;  // 2*log2(e)
    float e;
    asm("ex2.approx.f32 %0, %1;" : "=f"(e) : "f"(t));
    float r;
    asm("rcp.approx.f32 %0, %1;" : "=f"(r) : "f"(e + 1.0f));
    return 1.0f - 2.0f * r;
}
__device__ __forceinline__ float fast_exp(float x) {
    float t = x * 1.4426950408889634f;
    float e;
    asm("ex2.approx.f32 %0, %1;" : "=f"(e) : "f"(t));
    return e;
}
__device__ __forceinline__ uint32_t pack_h2(__half a, __half b) {
    __half2 v = __halves2half2(a, b);
    return *reinterpret_cast<uint32_t*>(&v);
}

// ---------------------------------------------------------------------------
// K0: fused prep. Blocks 0..511: convB row. Blocks 512..543: base[b,:].
// Block 544: both worklists.
// ---------------------------------------------------------------------------
__global__ __launch_bounds__(512) void prep_kernel(
    const float* __restrict__ W1, const float* __restrict__ summary,
    const float* __restrict__ b1, const int* __restrict__ tlen) {
    int blk = blockIdx.x;
    int tid = threadIdx.x;

    if (blk < 512) {
        g_Bf[blk * 512 + tid] = __float2half_rn(W1[(size_t)blk * NC + tid]);
    } else if (blk < 544) {
        int b = blk - 512;
        __shared__ float ss[512];
        ss[tid] = summary[b * 512 + tid];
        __syncthreads();
        const float* w = W1 + (size_t)tid * NC + 512;
        float acc = b1[tid];
#pragma unroll 8
        for (int c = 0; c < 512; c++) acc += ss[c] * w[c];
        g_base[b * NH + tid] = acc;
    } else if (tid < 32) {
        int len = tlen[tid];
        // GEMM worklist: 256-row tiles
        {
            int nt = (len + 255) >> 8;
            int off = nt;
#pragma unroll
            for (int d = 1; d < 32; d <<= 1) {
                int v = __shfl_up_sync(0xffffffffu, off, d);
                if (tid >= d) off += v;
            }
            int excl = off - nt;
            for (int t = 0; t < nt; t++) g_work[excl + t] = (tid << 4) | t;
            if (tid == 31) g_nwork = off;
        }
        // ctx worklist: 128-row tiles
        {
            int nt = (len + 127) >> 7;
            int off = nt;
#pragma unroll
            for (int d = 1; d < 32; d <<= 1) {
                int v = __shfl_up_sync(0xffffffffu, off, d);
                if (tid >= d) off += v;
            }
            int excl = off - nt;
            for (int t = 0; t < nt; t++) g_work2[excl + t] = (tid << 5) | t;
            if (tid == 31) g_nwork2 = off;
        }
    }
}

// ---------------------------------------------------------------------------
// K1: HMMA GEMM. 256m x 128n CTA, 512 threads = 16 warps (4m x 4n),
// warp tile 64m x 32n -> mma 4096 cyc/stage vs ldsm crossbar 3072 cyc/stage
// (tensor-bound). A staged per stage from fp32 ts with fused conversion
// (double-buffered); B cp.async double-buffered. Register logit partials.
// ---------------------------------------------------------------------------
__global__ __launch_bounds__(512, 1) void gemm_kernel(
    const float* __restrict__ ts, const float* __restrict__ W1,
    const float* __restrict__ W2, const float* __restrict__ coverage) {
    extern __shared__ char smem[];
    const uint32_t sb = smem_u32(smem);
    const int tid = threadIdx.x;
    const int lane = tid & 31;
    const int warp = tid >> 5;
    const int wm = warp & 3;   // m quarter (64 rows)
    const int wn = warp >> 2;  // n quarter (32 cols)

    if ((int)blockIdx.x >= g_nwork) return;
    const int wk = g_work[blockIdx.x];
    const int b = wk >> 4;
    const size_t m0 = (size_t)wk * MT2;

    float* s_w2 = (float*)(smem + SM_TAB);            // 512
    float* s_base = (float*)(smem + SM_TAB + 2048);   // 512
    float* s_wcov = (float*)(smem + SM_TAB + 4096);   // 512
    float* s_red = (float*)(smem + SM_TAB + 6144);    // 256 x 4

    // A-staging per-thread coords: 8192 float4 per stage, 16/thread in 8
    // groups of 2 (hooked into the k-step loop).
    // e = tid + (ks*2+j)*512 ; r = e>>5 (0..255), q = e&31 (float4 col)

    // ---- prologue: B stage 0 (async) + A stage 0 conversion + tables ----
    {
#pragma unroll
        for (int i = 0; i < 4; i++) {
            int e = tid + i * 512;
            int r = e >> 4, c = e & 15;
            cpasync16(sb + SM_B + (uint32_t)(r * ROW2 + c * 16),
                      g_Bf + (size_t)r * 512 + c * 8);
        }
        CP_COMMIT();

        // A stage 0 (kst=0): 16 float4 per thread, 4 groups of 4
#pragma unroll
        for (int gq = 0; gq < 4; gq++) {
            float4 v[4];
#pragma unroll
            for (int j = 0; j < 4; j++) {
                int e = tid + (gq * 4 + j) * 512;
                int r = e >> 5, q = e & 31;
                v[j] = *(const float4*)(ts + (m0 + r) * 512 + q * 4);
            }
#pragma unroll
            for (int j = 0; j < 4; j++) {
                int e = tid + (gq * 4 + j) * 512;
                int r = e >> 5, q = e & 31;
                *(uint2*)(smem + r * ROW2 + q * 8) = make_uint2(
                    pack_h2(__float2half_rn(v[j].x), __float2half_rn(v[j].y)),
                    pack_h2(__float2half_rn(v[j].z), __float2half_rn(v[j].w)));
            }
        }

        s_w2[tid] = W2[tid];
        s_base[tid] = g_base[b * NH + tid];
        s_wcov[tid] = W1[(size_t)tid * NC + 1024];
        CP_WAIT0();
        __syncthreads();
    }

    const uint32_t aBase =
        sb + (uint32_t)((wm * 64 + (lane & 15)) * ROW2 + (lane >> 4) * 16);
    const uint32_t bBase =
        sb + SM_B +
        (uint32_t)((wn * 32 + (lane & 7) + ((lane >> 4) & 1) * 8) * ROW2 +
                   ((lane >> 3) & 1) * 16);

    float acc[4][4][4];
#pragma unroll
    for (int i = 0; i < 4; i++)
#pragma unroll
        for (int j = 0; j < 4; j++)
#pragma unroll
            for (int c = 0; c < 4; c++) acc[i][j][c] = 0.0f;

    float rsum[4][2];
#pragma unroll
    for (int i = 0; i < 4; i++) rsum[i][0] = rsum[i][1] = 0.0f;

    const int crB = tid >> 4;  // B cp.async row base (0..31), +32 per i
    const int ccB = tid & 15;

    for (int g = 0; g < NST; g++) {
        const uint32_t abuf = (uint32_t)((g & 1) * A_TILE);
        const uint32_t bbuf = (uint32_t)((g & 1) * B_TILE);
        const bool pre = (g < NST - 1);
        const int gn = g + 1;
        const int htn = gn >> 2, kstn = gn & 3;
        const uint32_t nabuf = (uint32_t)((gn & 1) * A_TILE);
        const uint32_t nbbuf = (uint32_t)((gn & 1) * B_TILE);

        // next B stage (async)
        if (pre) {
#pragma unroll
            for (int i = 0; i < 4; i++) {
                int r = crB + i * 32;
                cpasync16(sb + SM_B + nbbuf + (uint32_t)(r * ROW2 + ccB * 16),
                          g_Bf + (size_t)(htn * 128 + r) * 512 + kstn * 128 +
                              ccB * 8);
            }
            CP_COMMIT();
        }

        // next A stage group 0 prefetch (2 float4)
        float4 av[2];
        if (pre) {
#pragma unroll
            for (int j = 0; j < 2; j++) {
                int e = tid + j * 512;
                int r = e >> 5, q = e & 31;
                av[j] = *(const float4*)(ts + (m0 + r) * 512 + kstn * 128 +
                                         q * 4);
            }
        }

#pragma unroll
        for (int ks = 0; ks < 8; ks++) {
            uint32_t a[4][4];
#pragma unroll
            for (int tm = 0; tm < 4; tm++)
                ldsm4(aBase + abuf + ks * 32 + tm * 16 * ROW2, a[tm][0],
                      a[tm][1], a[tm][2], a[tm][3]);
#pragma unroll
            for (int tp = 0; tp < 2; tp++) {
                uint32_t b0, b1, b2, b3;
                ldsm4(bBase + bbuf + ks * 32 + tp * 16 * ROW2, b0, b1, b2, b3);
#pragma unroll
                for (int tm = 0; tm < 4; tm++) {
                    mma16816(acc[tm][2 * tp], a[tm][0], a[tm][1], a[tm][2],
                             a[tm][3], b0, b1);
                    mma16816(acc[tm][2 * tp + 1], a[tm][0], a[tm][1], a[tm][2],
                             a[tm][3], b2, b3);
                }
            }

            // A conversion hook: store group ks, load group ks+1
            if (pre) {
#pragma unroll
                for (int j = 0; j < 2; j++) {
                    int e = tid + (ks * 2 + j) * 512;
                    int r = e >> 5, q = e & 31;
                    *(uint2*)(smem + nabuf + r * ROW2 + q * 8) = make_uint2(
                        pack_h2(__float2half_rn(av[j].x),
                                __float2half_rn(av[j].y)),
                        pack_h2(__float2half_rn(av[j].z),
                                __float2half_rn(av[j].w)));
                }
                if (ks < 7) {
#pragma unroll
                    for (int j = 0; j < 2; j++) {
                        int e = tid + ((ks + 1) * 2 + j) * 512;
                        int r = e >> 5, q = e & 31;
                        av[j] = *(const float4*)(ts + (m0 + r) * 512 +
                                                 kstn * 128 + q * 4);
                    }
                }
            }
        }

        // h-tile boundary: fold into register partials
        if ((g & 3) == 3) {
            const int h0 = (g >> 2) * 128;
#pragma unroll
            for (int tm = 0; tm < 4; tm++) {
#pragma unroll
                for (int rh = 0; rh < 2; rh++) {
                    int m_local = wm * 64 + tm * 16 + rh * 8 + (lane >> 2);
                    float cov = coverage[m0 + m_local];
                    float rs = 0.0f;
#pragma unroll
                    for (int tn = 0; tn < 4; tn++) {
                        int h = h0 + wn * 32 + tn * 8 + (lane & 3) * 2;
                        float p0 = acc[tm][tn][rh * 2 + 0] + s_base[h] +
                                   cov * s_wcov[h];
                        float p1 = acc[tm][tn][rh * 2 + 1] + s_base[h + 1] +
                                   cov * s_wcov[h + 1];
                        rs += fast_tanh(p0) * s_w2[h] +
                              fast_tanh(p1) * s_w2[h + 1];
                    }
                    rsum[tm][rh] += rs;
#pragma unroll
                    for (int tn = 0; tn < 4; tn++) {
                        acc[tm][tn][rh * 2 + 0] = 0.0f;
                        acc[tm][tn][rh * 2 + 1] = 0.0f;
                    }
                }
            }
        }

        if (pre) CP_WAIT0();
        __syncthreads();
    }

    // ---- final logit reduction ----
#pragma unroll
    for (int tm = 0; tm < 4; tm++) {
#pragma unroll
        for (int rh = 0; rh < 2; rh++) {
            float rs = rsum[tm][rh];
            rs += __shfl_xor_sync(0xffffffffu, rs, 1);
            rs += __shfl_xor_sync(0xffffffffu, rs, 2);
            int m_local = wm * 64 + tm * 16 + rh * 8 + (lane >> 2);
            if ((lane & 3) == 0) s_red[m_local * 4 + wn] = rs;
        }
    }
    __syncthreads();
    if (tid < 256)
        g_logits[m0 + tid] = (s_red[tid * 4] + s_red[tid * 4 + 1]) +
                             (s_red[tid * 4 + 2] + s_red[tid * 4 + 3]);
}

// ---------------------------------------------------------------------------
// K3: per-batch masked softmax (512 threads)
// ---------------------------------------------------------------------------
__global__ __launch_bounds__(512) void softmax_kernel(const int* __restrict__ tlen,
                                                      float* __restrict__ att_out) {
    int b = blockIdx.x;
    int tid = threadIdx.x;
    __shared__ float sl[NL];
    __shared__ float rbuf[512];
    int len = tlen[b];

    for (int l = tid; l < len; l += 512) sl[l] = g_logits[b * NL + l];
    __syncthreads();

    float mx = -INFINITY;
    for (int l = tid; l < len; l += 512) mx = fmaxf(mx, sl[l]);
    rbuf[tid] = mx;
    __syncthreads();
    for (int s = 256; s > 0; s >>= 1) {
        if (tid < s) rbuf[tid] = fmaxf(rbuf[tid], rbuf[tid + s]);
        __syncthreads();
    }
    mx = rbuf[0];
    __syncthreads();

    float sum = 0.0f;
    for (int l = tid; l < len; l += 512) {
        float e = fast_exp(sl[l] - mx);
        sl[l] = e;
        sum += e;
    }
    rbuf[tid] = sum;
    __syncthreads();
    for (int s = 256; s > 0; s >>= 1) {
        if (tid < s) rbuf[tid] = rbuf[tid] + rbuf[tid + s];
        __syncthreads();
    }
    float inv = 1.0f / rbuf[0];

    for (int l = tid; l < NL; l += 512)
        att_out[b * NL + l] = (l < len) ? sl[l] * inv : 0.0f;
}

// ---------------------------------------------------------------------------
// K4: context partials (128-grain worklist, float4 + 8-deep load batches)
// ---------------------------------------------------------------------------
__global__ __launch_bounds__(512) void ctx_part_kernel(
    const float* __restrict__ ts, const float* __restrict__ att) {
    if ((int)blockIdx.x >= g_nwork2) return;
    int wk = g_work2[blockIdx.x];
    int b = wk >> 5;
    int c = wk & 31;
    int tid = threadIdx.x;
    const int fq = tid & 127;
    const int lg = tid >> 7;

    __shared__ float sa[128];
    __shared__ float4 red[512];
    if (tid < 128) sa[tid] = att[b * NL + c * 128 + tid];
    __syncthreads();

    const float4* base =
        (const float4*)(ts + ((size_t)b * NL + c * 128) * 512) + fq;
    float4 acc = make_float4(0.f, 0.f, 0.f, 0.f);

#pragma unroll
    for (int bt = 0; bt < 4; bt++) {
        const int l0 = lg * 32 + bt * 8;
        float4 v[8];
#pragma unroll
        for (int j = 0; j < 8; j++) v[j] = base[(size_t)(l0 + j) * 128];
#pragma unroll
        for (int j = 0; j < 8; j++) {
            float w = sa[l0 + j];
            acc.x += w * v[j].x;
            acc.y += w * v[j].y;
            acc.z += w * v[j].z;
            acc.w += w * v[j].w;
        }
    }
    red[tid] = acc;
    __syncthreads();

    if (tid < 128) {
        float4 r0 = red[tid], r1 = red[tid + 128];
        float4 r2 = red[tid + 256], r3 = red[tid + 384];
        float4 s;
        s.x = (r0.x + r1.x) + (r2.x + r3.x);
        s.y = (r0.y + r1.y) + (r2.y + r3.y);
        s.z = (r0.z + r1.z) + (r2.z + r3.z);
        s.w = (r0.w + r1.w) + (r2.w + r3.w);
        *((float4*)(g_ctx_part + ((size_t)c * NB + b) * 512) + tid) = s;
    }
}

__global__ __launch_bounds__(512) void ctx_reduce_kernel(
    const int* __restrict__ tlen, float* __restrict__ ctx) {
    int b = blockIdx.x;
    int f = threadIdx.x;
    int nt = (tlen[b] + 127) >> 7;
    float s = 0.0f;
    for (int c = 0; c < nt; c++)
        s += g_ctx_part[((size_t)c * NB + b) * 512 + f];
    ctx[b * 512 + f] = s;
}

// ---------------------------------------------------------------------------
// Launch
// ---------------------------------------------------------------------------
extern "C" void kernel_launch(void* const* d_in, const int* in_sizes, int n_in,
                              void* d_out, int out_size) {
    const float* ts  = (const float*)d_in[0];
    const float* ss  = (const float*)d_in[1];
    const float* cov = (const float*)d_in[2];
    const float* W1  = (const float*)d_in[3];
    const float* b1  = (const float*)d_in[4];
    const float* W2  = (const float*)d_in[5];
    const int*   tl  = (const int*)d_in[7];
    float* out = (float*)d_out;
    float* ctx_out = out;             // [32,512]
    float* att_out = out + NB * 512;  // [32,4096]

    cudaFuncSetAttribute(gemm_kernel,
                         cudaFuncAttributeMaxDynamicSharedMemorySize, SMEM_TOTAL);

    prep_kernel<<<545, 512>>>(W1, ss, b1, tl);
    gemm_kernel<<<512, 512, SMEM_TOTAL>>>(ts, W1, W2, cov);
    softmax_kernel<<<NB, 512>>>(tl, att_out);
    ctx_part_kernel<<<1024, 512>>>(ts, att_out);
    ctx_reduce_kernel<<<NB, 512>>>(tl, ctx_out);
}